// round 12
// baseline (speedup 1.0000x reference)
#include <cuda_runtime.h>
#include <cuda_fp16.h>
#include <cstdint>

#define NNODES 100000
#define NPAD   100096          // 782 * 128, padded row count for scratch
#define HDIM   128
#define RWS    10
#define KHOPS  4
#define CDIM   40
#define NSAMP  (KHOPS * RWS)   // 40
#define NPB    16              // nodes per agg block (16 lanes each, 256 thr)

// Scratch buffers — __device__ globals (zero-init).
__device__ __half g_x16 [(size_t)NPAD * 256];   // x converted to fp16
__device__ __half g_bufA[(size_t)NPAD * HDIM];  // gemm out, fp16
__device__ __half g_bufB[(size_t)NPAD * HDIM];  // agg out, fp16
__device__ __half g_w0h[256 * 128];
__device__ __half g_w1h[128 * 128];
__device__ __half g_w2h[128 * 64];              // padded 40->64
__device__ float  g_sdeg[NNODES];
__device__ float  g_isdeg[NNODES];

__device__ __forceinline__ uint4 f8_to_h8(const float* f) {
    uint4 r;
    ((__half2*)&r.x)[0] = __floats2half2_rn(f[0], f[1]);
    ((__half2*)&r.x)[1] = __floats2half2_rn(f[2], f[3]);
    ((__half2*)&r.z)[0] = __floats2half2_rn(f[4], f[5]);
    ((__half2*)&r.z)[1] = __floats2half2_rn(f[6], f[7]);
    return r;
}

// ---------------------------------------------------------------------------
// Tensor-core + async-copy primitives
// ---------------------------------------------------------------------------
__device__ __forceinline__ uint32_t smem_u32(const void* p) {
    return (uint32_t)__cvta_generic_to_shared(p);
}
__device__ __forceinline__ void ldsm_x4(uint32_t* r, uint32_t a) {
    asm volatile("ldmatrix.sync.aligned.m8n8.x4.shared.b16 {%0,%1,%2,%3}, [%4];"
                 : "=r"(r[0]), "=r"(r[1]), "=r"(r[2]), "=r"(r[3]) : "r"(a));
}
__device__ __forceinline__ void ldsm_x4_t(uint32_t* r, uint32_t a) {
    asm volatile("ldmatrix.sync.aligned.m8n8.x4.trans.shared.b16 {%0,%1,%2,%3}, [%4];"
                 : "=r"(r[0]), "=r"(r[1]), "=r"(r[2]), "=r"(r[3]) : "r"(a));
}
__device__ __forceinline__ void mma16816(float* c, const uint32_t* a, const uint32_t* b) {
    asm volatile(
        "mma.sync.aligned.m16n8k16.row.col.f32.f16.f16.f32 "
        "{%0,%1,%2,%3}, {%4,%5,%6,%7}, {%8,%9}, {%0,%1,%2,%3};"
        : "+f"(c[0]), "+f"(c[1]), "+f"(c[2]), "+f"(c[3])
        : "r"(a[0]), "r"(a[1]), "r"(a[2]), "r"(a[3]), "r"(b[0]), "r"(b[1]));
}
__device__ __forceinline__ void cp16(uint32_t dst, const void* src) {
    asm volatile("cp.async.cg.shared.global [%0], [%1], 16;"
                 :: "r"(dst), "l"(src));
}
__device__ __forceinline__ void cp_commit() {
    asm volatile("cp.async.commit_group;");
}
template <int N>
__device__ __forceinline__ void cp_wait() {
    asm volatile("cp.async.wait_group %0;" :: "n"(N));
}

// ---------------------------------------------------------------------------
// Prep: deg sqrt/rsqrt + convert W0/W1/W2 to fp16 (W2 padded 40->64 cols).
// ---------------------------------------------------------------------------
__global__ void __launch_bounds__(256) prep_kernel(
    const float* __restrict__ deg,
    const float* __restrict__ W0, const float* __restrict__ W1,
    const float* __restrict__ W2)
{
    const int i = blockIdx.x * 256 + threadIdx.x;
    if (i < NNODES) {
        float d = deg[i];
        g_sdeg[i]  = sqrtf(d);
        g_isdeg[i] = rsqrtf(d);
    }
    if (i < 256 * 128) g_w0h[i] = __float2half_rn(W0[i]);
    if (i < 128 * 128) g_w1h[i] = __float2half_rn(W1[i]);
    if (i < 128 * 64) {
        const int r = i >> 6, c = i & 63;
        g_w2h[i] = (c < CDIM) ? __float2half_rn(W2[r * CDIM + c])
                              : __float2half_rn(0.0f);
    }
}

// ---------------------------------------------------------------------------
// x -> fp16 streaming convert.
// ---------------------------------------------------------------------------
__global__ void __launch_bounds__(256) cvt_x_kernel(
    const float4* __restrict__ x, uint2* __restrict__ out)
{
    const int i = blockIdx.x * 256 + threadIdx.x;   // one float4 each
    float4 v = x[i];
    uint2 h;
    ((__half2*)&h.x)[0] = __floats2half2_rn(v.x, v.y);
    ((__half2*)&h.y)[0] = __floats2half2_rn(v.z, v.w);
    out[i] = h;
}

// ---------------------------------------------------------------------------
// Pipelined fp16 HMMA GEMM: C[NPAD x 128] = A[NPAD x K] @ Wh[K x 128] + bias.
// BM=128, BN=128, BK=16, 256 threads, 8 warps (4x2), 32x64 per warp.
// A and B both streamed via cp.async 4-stage rings (wait_group 2).
// ---------------------------------------------------------------------------
template <int K>
__global__ void __launch_bounds__(256) hgemm_pipe(
    const __half* __restrict__ A, const __half* __restrict__ Wh,
    const float* __restrict__ bias, __half* __restrict__ C16)
{
    constexpr int S  = 4;
    constexpr int AP = 24;    // As row pitch (halves)
    constexpr int BP = 136;   // Bs row pitch (halves)
    constexpr int KT = K / 16;

    __shared__ __half As[S][128 * AP];
    __shared__ __half Bs[S][16 * BP];

    const int t    = threadIdx.x;
    const int lane = t & 31;
    const int wid  = t >> 5;
    const int warpRow = wid >> 1;
    const int warpCol = wid & 1;
    const int blockRow = blockIdx.x * 128;

    const int a_row = t >> 1;          // 0..127
    const int a_kg  = (t & 1) * 8;     // 0/8
    const int grow  = blockRow + a_row;

    const int b_r = t >> 4;            // 0..15
    const int b_n = (t & 15) * 8;      // 0..120

    auto issue = [&](int s, int k0) {
        cp16(smem_u32(&As[s][a_row * AP + a_kg]),
             A + (size_t)grow * K + k0 + a_kg);
        cp16(smem_u32(&Bs[s][b_r * BP + b_n]),
             Wh + (size_t)(k0 + b_r) * 128 + b_n);
        cp_commit();
    };

    issue(0, 0);
    issue(1, 16);
    issue(2, 32);

    float acc[2][8][4];
    #pragma unroll
    for (int mt = 0; mt < 2; mt++)
        #pragma unroll
        for (int nt = 0; nt < 8; nt++)
            #pragma unroll
            for (int q = 0; q < 4; q++) acc[mt][nt][q] = 0.0f;

    const int a_lr = lane & 15;
    const int a_lk = (lane >> 4) * 8;
    const int b_lr = (lane & 7) + ((lane >> 3) & 1) * 8;
    const int b_lcg = (lane >> 4) * 8;

    for (int kt = 0; kt < KT; kt++) {
        cp_wait<2>();
        __syncthreads();

        // Overlap next copy with this stage's compute. Target buffer
        // (kt+3)%4 was fully consumed last iteration (barrier above orders).
        if (kt + S - 1 < KT) issue((kt + S - 1) % S, (kt + S - 1) * 16);
        else                 cp_commit();

        const int rb = kt % S;
        uint32_t a[2][4];
        #pragma unroll
        for (int mt = 0; mt < 2; mt++) {
            ldsm_x4(a[mt], smem_u32(
                &As[rb][(warpRow * 32 + mt * 16 + a_lr) * AP + a_lk]));
        }

        uint32_t b[8][2];
        #pragma unroll
        for (int ntp = 0; ntp < 4; ntp++) {
            uint32_t r4[4];
            ldsm_x4_t(r4, smem_u32(
                &Bs[rb][b_lr * BP + warpCol * 64 + ntp * 16 + b_lcg]));
            b[ntp * 2 + 0][0] = r4[0]; b[ntp * 2 + 0][1] = r4[1];
            b[ntp * 2 + 1][0] = r4[2]; b[ntp * 2 + 1][1] = r4[3];
        }

        #pragma unroll
        for (int mt = 0; mt < 2; mt++)
            #pragma unroll
            for (int nt = 0; nt < 8; nt++)
                mma16816(acc[mt][nt], a[mt], b[nt]);
    }

    // Epilogue: bias (fp32) -> fp16 half2 stores. Padded scratch: no guards.
    float2 bb[8];
    #pragma unroll
    for (int nt = 0; nt < 8; nt++) {
        const int col = warpCol * 64 + nt * 8 + (lane & 3) * 2;
        bb[nt] = *(const float2*)&bias[col];
    }

    #pragma unroll
    for (int mt = 0; mt < 2; mt++) {
        const int r0 = blockRow + warpRow * 32 + mt * 16 + (lane >> 2);
        const int r1 = r0 + 8;
        #pragma unroll
        for (int nt = 0; nt < 8; nt++) {
            const int col = warpCol * 64 + nt * 8 + (lane & 3) * 2;
            *(__half2*)(C16 + (size_t)r0 * 128 + col) =
                __floats2half2_rn(acc[mt][nt][0] + bb[nt].x,
                                  acc[mt][nt][1] + bb[nt].y);
            *(__half2*)(C16 + (size_t)r1 * 128 + col) =
                __floats2half2_rn(acc[mt][nt][2] + bb[nt].x,
                                  acc[mt][nt][3] + bb[nt].y);
        }
    }
}

// ---------------------------------------------------------------------------
// Random-walk aggregation + ReLU (R8-validated design, ~70us).
// fp16 HFMA2 dual accumulators, fp32 combine. 256 threads = 16 nodes x
// 16 lanes; each lane owns 8 features (16B row slice, LDG.128 gathers).
// ---------------------------------------------------------------------------
__global__ void __launch_bounds__(256) agg_kernel(
    const __half* __restrict__ hin, __half* __restrict__ hout,
    const int* __restrict__ ends_l,
    const float* __restrict__ sdeg,
    const float* __restrict__ isdeg,
    const float* __restrict__ att_l)
{
    __shared__ int2 sp[NPB][NSAMP];     // {endpoint idx, half2(w,w) bits}

    const int n0 = blockIdx.x * NPB;
    const int t  = threadIdx.x;

    #pragma unroll
    for (int i = t; i < NPB * NSAMP; i += 256) {
        const int nl = i / NSAMP;
        const int s  = i - nl * NSAMP;
        const int k  = s / RWS;
        const int r  = s - k * RWS;
        const int n  = n0 + nl;
        const int e  = ends_l[k * (NNODES * RWS) + n * RWS + r];
        const float w = att_l[k + 1] * (1.0f / RWS) * sdeg[n] * isdeg[e];
        __half2 wh = __float2half2_rn(w);
        int2 p; p.x = e; p.y = *(int*)&wh;
        sp[nl][s] = p;
    }
    __syncthreads();

    const int nl   = t >> 4;
    const int lane = t & 15;
    const int n    = n0 + nl;
    const __half* lbase = hin + lane * 8;

    __half2 a0[4], a1[4];
    {
        const __half2 att0h = __float2half2_rn(att_l[0]);
        uint4 self = *(const uint4*)(hin + (size_t)n * HDIM + lane * 8);
        const __half2* sv = (const __half2*)&self;
        const __half2 z = __floats2half2_rn(0.f, 0.f);
        #pragma unroll
        for (int q = 0; q < 4; q++) { a0[q] = __hmul2(att0h, sv[q]); a1[q] = z; }
    }

    #pragma unroll
    for (int s = 0; s < NSAMP; s += 2) {
        const int2 p0 = sp[nl][s];
        const int2 p1 = sp[nl][s + 1];
        uint4 v0 = *(const uint4*)(lbase + ((size_t)p0.x << 7));
        uint4 v1 = *(const uint4*)(lbase + ((size_t)p1.x << 7));
        const __half2 w0 = *(const __half2*)&p0.y;
        const __half2 w1 = *(const __half2*)&p1.y;
        const __half2* e0 = (const __half2*)&v0;
        const __half2* e1 = (const __half2*)&v1;
        #pragma unroll
        for (int q = 0; q < 4; q++) {
            a0[q] = __hfma2(w0, e0[q], a0[q]);
            a1[q] = __hfma2(w1, e1[q], a1[q]);
        }
    }

    float f[8];
    #pragma unroll
    for (int q = 0; q < 4; q++) {
        float2 u = __half22float2(a0[q]);
        float2 v = __half22float2(a1[q]);
        f[q * 2 + 0] = fmaxf(u.x + v.x, 0.0f);
        f[q * 2 + 1] = fmaxf(u.y + v.y, 0.0f);
    }
    *(uint4*)(hout + (size_t)n * HDIM + lane * 8) = f8_to_h8(f);
}

// ---------------------------------------------------------------------------
// Final: logits = h @ W2 + b2 (HMMA, N padded 40->64), fused log_softmax.
// BM=64, 4 warps, warp tile 16x64. Padded cols: bias -1e30 -> never max.
// ---------------------------------------------------------------------------
__global__ void __launch_bounds__(128) final_kernel(
    const __half* __restrict__ h,
    const float* __restrict__ b2, float* __restrict__ out, int M)
{
    constexpr int AP = 136;  // As pitch (rows of 128 halves)
    constexpr int BP = 72;   // Bs pitch (rows of 64 halves)
    __shared__ __half As[64 * AP];
    __shared__ __half Bs[128 * BP];

    const int t    = threadIdx.x;
    const int lane = t & 31;
    const int wid  = t >> 5;
    const int blockRow = blockIdx.x * 64;

    // Stage B: pre-padded fp16 W2 [128 x 64].
    {
        const uint4* src = (const uint4*)&g_w2h[t * 64];
        #pragma unroll
        for (int q = 0; q < 8; q++)
            *(uint4*)&Bs[t * BP + q * 8] = src[q];
    }
    // Stage A: h rows [blockRow..+63] x 128 halves (padded buffer, no guard).
    {
        const int a_row = t >> 1;
        const int kg    = (t & 1) * 64;
        const uint4* src = (const uint4*)(h + (size_t)(blockRow + a_row) * HDIM + kg);
        #pragma unroll
        for (int q = 0; q < 8; q++)
            *(uint4*)&As[a_row * AP + kg + q * 8] = src[q];
    }
    __syncthreads();

    const int a_lr = lane & 15;
    const int a_lk = (lane >> 4) * 8;
    const int b_lr = (lane & 7) + ((lane >> 3) & 1) * 8;
    const int b_lcg = (lane >> 4) * 8;

    float acc[8][4];
    #pragma unroll
    for (int nt = 0; nt < 8; nt++)
        #pragma unroll
        for (int q = 0; q < 4; q++) acc[nt][q] = 0.0f;

    #pragma unroll
    for (int k0 = 0; k0 < HDIM; k0 += 16) {
        uint32_t a[4];
        ldsm_x4(a, smem_u32(&As[(wid * 16 + a_lr) * AP + k0 + a_lk]));

        uint32_t b[8][2];
        #pragma unroll
        for (int ntp = 0; ntp < 4; ntp++) {
            uint32_t r4[4];
            ldsm_x4_t(r4, smem_u32(&Bs[(k0 + b_lr) * BP + ntp * 16 + b_lcg]));
            b[ntp * 2 + 0][0] = r4[0]; b[ntp * 2 + 0][1] = r4[1];
            b[ntp * 2 + 1][0] = r4[2]; b[ntp * 2 + 1][1] = r4[3];
        }

        #pragma unroll
        for (int nt = 0; nt < 8; nt++)
            mma16816(acc[nt], a, b[nt]);
    }

    float v0[8][2], v1[8][2];
    #pragma unroll
    for (int nt = 0; nt < 8; nt++) {
        const int col = nt * 8 + (lane & 3) * 2;
        const float bx = (col     < CDIM) ? b2[col]     : -1e30f;
        const float by = (col + 1 < CDIM) ? b2[col + 1] : -1e30f;
        v0[nt][0] = acc[nt][0] + bx; v0[nt][1] = acc[nt][1] + by;
        v1[nt][0] = acc[nt][2] + bx; v1[nt][1] = acc[nt][3] + by;
    }

    float m0 = -1e30f, m1 = -1e30f;
    #pragma unroll
    for (int nt = 0; nt < 8; nt++) {
        m0 = fmaxf(m0, fmaxf(v0[nt][0], v0[nt][1]));
        m1 = fmaxf(m1, fmaxf(v1[nt][0], v1[nt][1]));
    }
    m0 = fmaxf(m0, __shfl_xor_sync(0xffffffffu, m0, 1));
    m0 = fmaxf(m0, __shfl_xor_sync(0xffffffffu, m0, 2));
    m1 = fmaxf(m1, __shfl_xor_sync(0xffffffffu, m1, 1));
    m1 = fmaxf(m1, __shfl_xor_sync(0xffffffffu, m1, 2));

    float s0 = 0.0f, s1 = 0.0f;
    #pragma unroll
    for (int nt = 0; nt < 8; nt++) {
        s0 += __expf(v0[nt][0] - m0) + __expf(v0[nt][1] - m0);
        s1 += __expf(v1[nt][0] - m1) + __expf(v1[nt][1] - m1);
    }
    s0 += __shfl_xor_sync(0xffffffffu, s0, 1);
    s0 += __shfl_xor_sync(0xffffffffu, s0, 2);
    s1 += __shfl_xor_sync(0xffffffffu, s1, 1);
    s1 += __shfl_xor_sync(0xffffffffu, s1, 2);

    const float lse0 = m0 + __logf(s0);
    const float lse1 = m1 + __logf(s1);

    const int r0 = blockRow + wid * 16 + (lane >> 2);
    const int r1 = r0 + 8;
    #pragma unroll
    for (int nt = 0; nt < 5; nt++) {        // cols 0..39 only
        const int col = nt * 8 + (lane & 3) * 2;
        if (r0 < M) {
            float2 w = make_float2(v0[nt][0] - lse0, v0[nt][1] - lse0);
            *(float2*)(out + (size_t)r0 * CDIM + col) = w;
        }
        if (r1 < M) {
            float2 w = make_float2(v1[nt][0] - lse1, v1[nt][1] - lse1);
            *(float2*)(out + (size_t)r1 * CDIM + col) = w;
        }
    }
}

// ---------------------------------------------------------------------------
// Launch sequence. Inputs: x, degree, ends, att, W0, b0, W1, b1, W2, b2
// ---------------------------------------------------------------------------
extern "C" void kernel_launch(void* const* d_in, const int* in_sizes, int n_in,
                              void* d_out, int out_size)
{
    const float* x   = (const float*)d_in[0];
    const float* deg = (const float*)d_in[1];
    const int*   ends= (const int*)  d_in[2];
    const float* att = (const float*)d_in[3];
    const float* W0  = (const float*)d_in[4];
    const float* b0  = (const float*)d_in[5];
    const float* W1  = (const float*)d_in[6];
    const float* b1  = (const float*)d_in[7];
    const float* W2  = (const float*)d_in[8];
    const float* b2  = (const float*)d_in[9];
    float* out = (float*)d_out;

    __half *x16, *bufA, *bufB, *w0h, *w1h;
    float *sdeg, *isdeg;
    cudaGetSymbolAddress((void**)&x16,  g_x16);
    cudaGetSymbolAddress((void**)&bufA, g_bufA);
    cudaGetSymbolAddress((void**)&bufB, g_bufB);
    cudaGetSymbolAddress((void**)&w0h,  g_w0h);
    cudaGetSymbolAddress((void**)&w1h,  g_w1h);
    cudaGetSymbolAddress((void**)&sdeg, g_sdeg);
    cudaGetSymbolAddress((void**)&isdeg,g_isdeg);

    const int gridM   = NPAD / 128;               // 782
    const int gridF   = (NNODES + 63) / 64;       // 1563
    const int gridAgg = NNODES / NPB;             // 6250
    const int gridX   = (NNODES * 256 / 4) / 256; // 25000

    prep_kernel<<<(NNODES + 255) / 256, 256>>>(deg, W0, W1, W2);
    cvt_x_kernel<<<gridX, 256>>>((const float4*)x, (uint2*)x16);
    // Layer 0: h = x16 @ W0h + b0 -> bufA (fp16)
    hgemm_pipe<256><<<gridM, 256>>>(x16, w0h, b0, bufA);
    // Agg layer 0: bufA -> bufB
    agg_kernel<<<gridAgg, 256>>>(bufA, bufB,
                                 ends + 0 * (size_t)KHOPS * NNODES * RWS,
                                 sdeg, isdeg, att + 0 * (KHOPS + 1));
    // Layer 1: h = bufB @ W1h + b1 -> bufA
    hgemm_pipe<128><<<gridM, 256>>>(bufB, w1h, b1, bufA);
    // Agg layer 1: bufA -> bufB
    agg_kernel<<<gridAgg, 256>>>(bufA, bufB,
                                 ends + 1 * (size_t)KHOPS * NNODES * RWS,
                                 sdeg, isdeg, att + 1 * (KHOPS + 1));
    // Final: logits + fused log_softmax -> out
    final_kernel<<<gridF, 128>>>(bufB, b2, out, NNODES);
}

// round 13
// speedup vs baseline: 1.2905x; 1.2905x over previous
#include <cuda_runtime.h>
#include <cuda_fp16.h>
#include <cstdint>

#define NNODES 100000
#define NPAD   100096          // 782 * 128, padded row count for scratch
#define HDIM   128
#define RWS    10
#define KHOPS  4
#define CDIM   40
#define NSAMP  (KHOPS * RWS)   // 40
#define NPB    16              // nodes per agg block (16 lanes each, 256 thr)

// Scratch ping-pong buffers in fp16 — __device__ globals (zero-init).
__device__ __half g_bufA[(size_t)NPAD * HDIM];
__device__ __half g_bufB[(size_t)NPAD * HDIM];
__device__ float  g_sdeg[NNODES];    // sqrt(deg)
__device__ float  g_isdeg[NNODES];   // rsqrt(deg)

__device__ __forceinline__ uint4 f8_to_h8(const float* f) {
    uint4 r;
    ((__half2*)&r.x)[0] = __floats2half2_rn(f[0], f[1]);
    ((__half2*)&r.x)[1] = __floats2half2_rn(f[2], f[3]);
    ((__half2*)&r.z)[0] = __floats2half2_rn(f[4], f[5]);
    ((__half2*)&r.z)[1] = __floats2half2_rn(f[6], f[7]);
    return r;
}

// ---------------------------------------------------------------------------
// Tensor-core + async-copy primitives
// ---------------------------------------------------------------------------
__device__ __forceinline__ uint32_t smem_u32(const void* p) {
    return (uint32_t)__cvta_generic_to_shared(p);
}
__device__ __forceinline__ void ldsm_x4(uint32_t* r, uint32_t a) {
    asm volatile("ldmatrix.sync.aligned.m8n8.x4.shared.b16 {%0,%1,%2,%3}, [%4];"
                 : "=r"(r[0]), "=r"(r[1]), "=r"(r[2]), "=r"(r[3]) : "r"(a));
}
__device__ __forceinline__ void ldsm_x4_t(uint32_t* r, uint32_t a) {
    asm volatile("ldmatrix.sync.aligned.m8n8.x4.trans.shared.b16 {%0,%1,%2,%3}, [%4];"
                 : "=r"(r[0]), "=r"(r[1]), "=r"(r[2]), "=r"(r[3]) : "r"(a));
}
__device__ __forceinline__ void mma16816(float* c, const uint32_t* a, const uint32_t* b) {
    asm volatile(
        "mma.sync.aligned.m16n8k16.row.col.f32.f16.f16.f32 "
        "{%0,%1,%2,%3}, {%4,%5,%6,%7}, {%8,%9}, {%0,%1,%2,%3};"
        : "+f"(c[0]), "+f"(c[1]), "+f"(c[2]), "+f"(c[3])
        : "r"(a[0]), "r"(a[1]), "r"(a[2]), "r"(a[3]), "r"(b[0]), "r"(b[1]));
}
__device__ __forceinline__ void cp16(uint32_t dst, const void* src) {
    asm volatile("cp.async.cg.shared.global [%0], [%1], 16;"
                 :: "r"(dst), "l"(src));
}
__device__ __forceinline__ void cp16z(uint32_t dst, const void* src, int sz) {
    asm volatile("cp.async.cg.shared.global [%0], [%1], 16, %2;"
                 :: "r"(dst), "l"(src), "r"(sz));
}
__device__ __forceinline__ void cp_commit() {
    asm volatile("cp.async.commit_group;");
}
template <int N>
__device__ __forceinline__ void cp_wait() {
    asm volatile("cp.async.wait_group %0;" :: "n"(N));
}

// ---------------------------------------------------------------------------
// Degree precompute: sqrt(deg), rsqrt(deg)
// ---------------------------------------------------------------------------
__global__ void __launch_bounds__(256) deg_prep_kernel(
    const float* __restrict__ deg, float* __restrict__ sdeg,
    float* __restrict__ isdeg)
{
    int i = blockIdx.x * 256 + threadIdx.x;
    if (i < NNODES) {
        float d = deg[i];
        sdeg[i]  = sqrtf(d);
        isdeg[i] = rsqrtf(d);
    }
}

// ---------------------------------------------------------------------------
// Pipelined HMMA GEMM: C[NPAD x 128] = A[. x K] @ W[K x 128] + bias.
// BM=128, BN=128, BK=16, 256 threads, 8 warps (4x2), 32x64 per warp.
// W staged fully into smem fp16 at start. A streamed via cp.async 4-stage
// ring, wait_group 2, next-stage copy issued BEFORE current-stage MMAs.
// fp32 A staged raw + converted in-smem. (R8-validated, 256.9us config.)
// ---------------------------------------------------------------------------
template <typename TA, int K>
__global__ void __launch_bounds__(256) hgemm_pipe(
    const TA* __restrict__ A, const float* __restrict__ W,
    const float* __restrict__ bias, __half* __restrict__ C, int M)
{
    constexpr bool F32A = (sizeof(TA) == 4);
    constexpr int  S  = 4;        // cp.async stages
    constexpr int  AP = 24;       // As row pitch (halves)
    constexpr int  BP = 136;      // Bs row pitch (halves)
    constexpr int  KT = K / 16;

    __shared__ __half Bs[K * BP];                       // full W, fp16
    __shared__ __half As[F32A ? 2 : S][128 * AP];       // ldmatrix A tiles
    __shared__ float  A32[F32A ? S * 128 * 16 : 1];     // raw fp32 staging

    const int t    = threadIdx.x;
    const int lane = t & 31;
    const int wid  = t >> 5;
    const int warpRow = wid >> 1;
    const int warpCol = wid & 1;
    const int blockRow = blockIdx.x * 128;

    const int a_row = t >> 1;
    const int a_kg  = (t & 1) * 8;
    const int grow  = blockRow + a_row;
    const bool a_valid = (grow < M);

    auto issueA = [&](int s, int k0) {
        if constexpr (F32A) {
            const float* src = A + (size_t)grow * K + k0 + a_kg;
            uint32_t d = smem_u32(&A32[s * 2048 + a_row * 16 + a_kg]);
            const int sz = a_valid ? 16 : 0;
            cp16z(d,      src,     sz);
            cp16z(d + 16, src + 4, sz);
        } else {
            const __half* src = (const __half*)A + (size_t)grow * K + k0 + a_kg;
            cp16(smem_u32(&As[s][a_row * AP + a_kg]), src);
        }
        cp_commit();
    };

    // Prologue: launch first S-1 A stages, then stage W while they fly.
    issueA(0, 0);
    issueA(1, 16);
    issueA(2, 32);

    for (int idx = t * 8; idx < K * 128; idx += 2048) {
        const int row = idx >> 7;
        const int col = idx & 127;
        const float* p = W + row * 128 + col;
        float4 v0 = *(const float4*)p;
        float4 v1 = *(const float4*)(p + 4);
        __half h8[8];
        h8[0] = __float2half_rn(v0.x); h8[1] = __float2half_rn(v0.y);
        h8[2] = __float2half_rn(v0.z); h8[3] = __float2half_rn(v0.w);
        h8[4] = __float2half_rn(v1.x); h8[5] = __float2half_rn(v1.y);
        h8[6] = __float2half_rn(v1.z); h8[7] = __float2half_rn(v1.w);
        *(uint4*)&Bs[row * BP + col] = *(uint4*)h8;
    }
    __syncthreads();    // Bs visible to all

    float acc[2][8][4];
    #pragma unroll
    for (int mt = 0; mt < 2; mt++)
        #pragma unroll
        for (int nt = 0; nt < 8; nt++)
            #pragma unroll
            for (int q = 0; q < 4; q++) acc[mt][nt][q] = 0.0f;

    const int a_lr = lane & 15;
    const int a_lk = (lane >> 4) * 8;
    const int b_lr = (lane & 7) + ((lane >> 3) & 1) * 8;
    const int b_lcg = (lane >> 4) * 8;

    for (int kt = 0; kt < KT; kt++) {
        cp_wait<2>();        // stage kt's copies done
        __syncthreads();     // ... visible to all threads

        // Issue stage kt+S-1 immediately (overlaps this stage's compute).
        if (kt + S - 1 < KT) issueA((kt + S - 1) % S, (kt + S - 1) * 16);
        else                 cp_commit();   // keep group counts aligned

        int rb;
        if constexpr (F32A) {
            rb = kt & 1;
            const float* s32 = &A32[(kt % S) * 2048 + a_row * 16 + a_kg];
            float4 v0 = *(const float4*)s32;
            float4 v1 = *(const float4*)(s32 + 4);
            __half h8[8];
            h8[0] = __float2half_rn(v0.x); h8[1] = __float2half_rn(v0.y);
            h8[2] = __float2half_rn(v0.z); h8[3] = __float2half_rn(v0.w);
            h8[4] = __float2half_rn(v1.x); h8[5] = __float2half_rn(v1.y);
            h8[6] = __float2half_rn(v1.z); h8[7] = __float2half_rn(v1.w);
            *(uint4*)&As[rb][a_row * AP + a_kg] = *(uint4*)h8;
            __syncthreads();
        } else {
            rb = kt % S;
        }

        uint32_t a[2][4];
        #pragma unroll
        for (int mt = 0; mt < 2; mt++) {
            ldsm_x4(a[mt], smem_u32(
                &As[rb][(warpRow * 32 + mt * 16 + a_lr) * AP + a_lk]));
        }

        uint32_t b[8][2];
        #pragma unroll
        for (int ntp = 0; ntp < 4; ntp++) {
            uint32_t r4[4];
            ldsm_x4_t(r4, smem_u32(
                &Bs[(kt * 16 + b_lr) * BP + warpCol * 64 + ntp * 16 + b_lcg]));
            b[ntp * 2 + 0][0] = r4[0]; b[ntp * 2 + 0][1] = r4[1];
            b[ntp * 2 + 1][0] = r4[2]; b[ntp * 2 + 1][1] = r4[3];
        }

        #pragma unroll
        for (int mt = 0; mt < 2; mt++)
            #pragma unroll
            for (int nt = 0; nt < 8; nt++)
                mma16816(acc[mt][nt], a[mt], b[nt]);
    }

    // Epilogue: add bias (fp32), store fp16. C is padded scratch: no guards.
    float2 bb[8];
    #pragma unroll
    for (int nt = 0; nt < 8; nt++) {
        const int col = warpCol * 64 + nt * 8 + (lane & 3) * 2;
        bb[nt] = *(const float2*)&bias[col];
    }

    #pragma unroll
    for (int mt = 0; mt < 2; mt++) {
        const int r0 = blockRow + warpRow * 32 + mt * 16 + (lane >> 2);
        const int r1 = r0 + 8;
        #pragma unroll
        for (int nt = 0; nt < 8; nt++) {
            const int col = warpCol * 64 + nt * 8 + (lane & 3) * 2;
            __half2 v0 = __floats2half2_rn(acc[mt][nt][0] + bb[nt].x,
                                           acc[mt][nt][1] + bb[nt].y);
            *(__half2*)(C + (size_t)r0 * 128 + col) = v0;
            __half2 v1 = __floats2half2_rn(acc[mt][nt][2] + bb[nt].x,
                                           acc[mt][nt][3] + bb[nt].y);
            *(__half2*)(C + (size_t)r1 * 128 + col) = v1;
        }
    }
}

// ---------------------------------------------------------------------------
// Random-walk aggregation + ReLU. fp16 HFMA2 dual accumulators, fp32 combine.
// 256 threads = 16 nodes x 16 lanes. 8 gather loads batched per iteration
// (MLP=8 — R12 post-mortem showed this kernel is L1tex-latency bound and
// MLP 2->4 was worth 24us/pass; extending along the validated axis).
// ---------------------------------------------------------------------------
__global__ void __launch_bounds__(256) agg_kernel(
    const __half* __restrict__ hin, __half* __restrict__ hout,
    const int* __restrict__ ends_l,
    const float* __restrict__ sdeg,
    const float* __restrict__ isdeg,
    const float* __restrict__ att_l)
{
    __shared__ int2 sp[NPB][NSAMP];     // {endpoint idx, half2(w,w) bits}

    const int n0 = blockIdx.x * NPB;
    const int t  = threadIdx.x;

    #pragma unroll
    for (int i = t; i < NPB * NSAMP; i += 256) {
        const int nl = i / NSAMP;
        const int s  = i - nl * NSAMP;
        const int k  = s / RWS;
        const int r  = s - k * RWS;
        const int n  = n0 + nl;
        const int e  = ends_l[k * (NNODES * RWS) + n * RWS + r];
        const float w = att_l[k + 1] * (1.0f / RWS) * sdeg[n] * isdeg[e];
        __half2 wh = __float2half2_rn(w);
        int2 p; p.x = e; p.y = *(int*)&wh;
        sp[nl][s] = p;
    }
    __syncthreads();

    const int nl   = t >> 4;
    const int lane = t & 15;
    const int n    = n0 + nl;
    const __half* lbase = hin + lane * 8;

    __half2 a0[4], a1[4];
    {
        const __half2 att0h = __float2half2_rn(att_l[0]);
        uint4 self = *(const uint4*)(hin + (size_t)n * HDIM + lane * 8);
        const __half2* sv = (const __half2*)&self;
        const __half2 z = __floats2half2_rn(0.f, 0.f);
        #pragma unroll
        for (int q = 0; q < 4; q++) { a0[q] = __hmul2(att0h, sv[q]); a1[q] = z; }
    }

    #pragma unroll
    for (int s = 0; s < NSAMP; s += 8) {
        int2  pp[8];
        uint4 vv[8];
        #pragma unroll
        for (int j = 0; j < 8; j++) pp[j] = sp[nl][s + j];
        #pragma unroll
        for (int j = 0; j < 8; j++)
            vv[j] = *(const uint4*)(lbase + ((size_t)pp[j].x << 7));
        #pragma unroll
        for (int j = 0; j < 8; j += 2) {
            const __half2 w0 = *(const __half2*)&pp[j].y;
            const __half2 w1 = *(const __half2*)&pp[j + 1].y;
            const __half2* e0 = (const __half2*)&vv[j];
            const __half2* e1 = (const __half2*)&vv[j + 1];
            #pragma unroll
            for (int q = 0; q < 4; q++) {
                a0[q] = __hfma2(w0, e0[q], a0[q]);
                a1[q] = __hfma2(w1, e1[q], a1[q]);
            }
        }
    }

    float f[8];
    #pragma unroll
    for (int q = 0; q < 4; q++) {
        float2 u = __half22float2(a0[q]);
        float2 v = __half22float2(a1[q]);
        f[q * 2 + 0] = fmaxf(u.x + v.x, 0.0f);
        f[q * 2 + 1] = fmaxf(u.y + v.y, 0.0f);
    }
    *(uint4*)(hout + (size_t)n * HDIM + lane * 8) = f8_to_h8(f);
}

// ---------------------------------------------------------------------------
// Final: logits = h @ W2 + b2 (HMMA, N padded 40->64), fused log_softmax.
// BM=64, 4 warps, warp tile 16x64. Padded cols: bias -1e30 -> never max.
// ---------------------------------------------------------------------------
__global__ void __launch_bounds__(128) final_kernel(
    const __half* __restrict__ h, const float* __restrict__ W2,
    const float* __restrict__ b2, float* __restrict__ out, int M)
{
    constexpr int AP = 136;  // As pitch (rows of 128 halves)
    constexpr int BP = 72;   // Bs pitch (rows of 64 halves)
    __shared__ __half As[64 * AP];
    __shared__ __half Bs[128 * BP];

    const int t    = threadIdx.x;
    const int lane = t & 31;
    const int wid  = t >> 5;
    const int blockRow = blockIdx.x * 64;

    // Stage B: W2 [128 k x 40] -> padded fp16 [128 x 64].
    {
        const int r = t;
        __half h8[8];
        #pragma unroll
        for (int c0 = 0; c0 < 64; c0 += 8) {
            #pragma unroll
            for (int q = 0; q < 8; q++) {
                const int c = c0 + q;
                h8[q] = (c < CDIM) ? __float2half_rn(W2[r * CDIM + c])
                                   : __float2half_rn(0.0f);
            }
            *(uint4*)&Bs[r * BP + c0] = *(uint4*)h8;
        }
    }

    // Stage A: h rows [blockRow..+63] x 128 halves (padded buffer, no guard).
    {
        const int a_row = t >> 1;
        const int kg    = (t & 1) * 64;
        const uint4* src = (const uint4*)(h + (size_t)(blockRow + a_row) * HDIM + kg);
        #pragma unroll
        for (int q = 0; q < 8; q++)
            *(uint4*)&As[a_row * AP + kg + q * 8] = src[q];
    }
    __syncthreads();

    const int a_lr = lane & 15;
    const int a_lk = (lane >> 4) * 8;
    const int b_lr = (lane & 7) + ((lane >> 3) & 1) * 8;
    const int b_lcg = (lane >> 4) * 8;

    float acc[8][4];
    #pragma unroll
    for (int nt = 0; nt < 8; nt++)
        #pragma unroll
        for (int q = 0; q < 4; q++) acc[nt][q] = 0.0f;

    #pragma unroll
    for (int k0 = 0; k0 < HDIM; k0 += 16) {
        uint32_t a[4];
        ldsm_x4(a, smem_u32(&As[(wid * 16 + a_lr) * AP + k0 + a_lk]));

        uint32_t b[8][2];
        #pragma unroll
        for (int ntp = 0; ntp < 4; ntp++) {
            uint32_t r4[4];
            ldsm_x4_t(r4, smem_u32(&Bs[(k0 + b_lr) * BP + ntp * 16 + b_lcg]));
            b[ntp * 2 + 0][0] = r4[0]; b[ntp * 2 + 0][1] = r4[1];
            b[ntp * 2 + 1][0] = r4[2]; b[ntp * 2 + 1][1] = r4[3];
        }

        #pragma unroll
        for (int nt = 0; nt < 8; nt++)
            mma16816(acc[nt], a, b[nt]);
    }

    float v0[8][2], v1[8][2];
    #pragma unroll
    for (int nt = 0; nt < 8; nt++) {
        const int col = nt * 8 + (lane & 3) * 2;
        const float bx = (col     < CDIM) ? b2[col]     : -1e30f;
        const float by = (col + 1 < CDIM) ? b2[col + 1] : -1e30f;
        v0[nt][0] = acc[nt][0] + bx; v0[nt][1] = acc[nt][1] + by;
        v1[nt][0] = acc[nt][2] + bx; v1[nt][1] = acc[nt][3] + by;
    }

    float m0 = -1e30f, m1 = -1e30f;
    #pragma unroll
    for (int nt = 0; nt < 8; nt++) {
        m0 = fmaxf(m0, fmaxf(v0[nt][0], v0[nt][1]));
        m1 = fmaxf(m1, fmaxf(v1[nt][0], v1[nt][1]));
    }
    m0 = fmaxf(m0, __shfl_xor_sync(0xffffffffu, m0, 1));
    m0 = fmaxf(m0, __shfl_xor_sync(0xffffffffu, m0, 2));
    m1 = fmaxf(m1, __shfl_xor_sync(0xffffffffu, m1, 1));
    m1 = fmaxf(m1, __shfl_xor_sync(0xffffffffu, m1, 2));

    float s0 = 0.0f, s1 = 0.0f;
    #pragma unroll
    for (int nt = 0; nt < 8; nt++) {
        s0 += __expf(v0[nt][0] - m0) + __expf(v0[nt][1] - m0);
        s1 += __expf(v1[nt][0] - m1) + __expf(v1[nt][1] - m1);
    }
    s0 += __shfl_xor_sync(0xffffffffu, s0, 1);
    s0 += __shfl_xor_sync(0xffffffffu, s0, 2);
    s1 += __shfl_xor_sync(0xffffffffu, s1, 1);
    s1 += __shfl_xor_sync(0xffffffffu, s1, 2);

    const float lse0 = m0 + __logf(s0);
    const float lse1 = m1 + __logf(s1);

    const int r0 = blockRow + wid * 16 + (lane >> 2);
    const int r1 = r0 + 8;
    #pragma unroll
    for (int nt = 0; nt < 5; nt++) {        // cols 0..39 only
        const int col = nt * 8 + (lane & 3) * 2;
        if (r0 < M) {
            float2 w = make_float2(v0[nt][0] - lse0, v0[nt][1] - lse0);
            *(float2*)(out + (size_t)r0 * CDIM + col) = w;
        }
        if (r1 < M) {
            float2 w = make_float2(v1[nt][0] - lse1, v1[nt][1] - lse1);
            *(float2*)(out + (size_t)r1 * CDIM + col) = w;
        }
    }
}

// ---------------------------------------------------------------------------
// Launch sequence. Inputs: x, degree, ends, att, W0, b0, W1, b1, W2, b2
// ---------------------------------------------------------------------------
extern "C" void kernel_launch(void* const* d_in, const int* in_sizes, int n_in,
                              void* d_out, int out_size)
{
    const float* x   = (const float*)d_in[0];
    const float* deg = (const float*)d_in[1];
    const int*   ends= (const int*)  d_in[2];
    const float* att = (const float*)d_in[3];
    const float* W0  = (const float*)d_in[4];
    const float* b0  = (const float*)d_in[5];
    const float* W1  = (const float*)d_in[6];
    const float* b1  = (const float*)d_in[7];
    const float* W2  = (const float*)d_in[8];
    const float* b2  = (const float*)d_in[9];
    float* out = (float*)d_out;

    __half *bufA = nullptr, *bufB = nullptr;
    float *sdeg = nullptr, *isdeg = nullptr;
    cudaGetSymbolAddress((void**)&bufA, g_bufA);
    cudaGetSymbolAddress((void**)&bufB, g_bufB);
    cudaGetSymbolAddress((void**)&sdeg, g_sdeg);
    cudaGetSymbolAddress((void**)&isdeg, g_isdeg);

    const int gridM   = NPAD / 128;               // 782
    const int gridF   = (NNODES + 63) / 64;       // 1563
    const int gridAgg = NNODES / NPB;             // 6250

    deg_prep_kernel<<<(NNODES + 255) / 256, 256>>>(deg, sdeg, isdeg);
    // Layer 0: h = x @ W0 + b0  -> bufA (fp16, cp.async-pipelined HMMA)
    hgemm_pipe<float, 256><<<gridM, 256>>>(x, W0, b0, bufA, NNODES);
    // Agg layer 0: bufA -> bufB (relu'd)
    agg_kernel<<<gridAgg, 256>>>(bufA, bufB,
                                 ends + 0 * (size_t)KHOPS * NNODES * RWS,
                                 sdeg, isdeg, att + 0 * (KHOPS + 1));
    // Layer 1: h = bufB @ W1 + b1 -> bufA
    hgemm_pipe<__half, 128><<<gridM, 256>>>(bufB, W1, b1, bufA, NNODES);
    // Agg layer 1: bufA -> bufB (relu'd)
    agg_kernel<<<gridAgg, 256>>>(bufA, bufB,
                                 ends + 1 * (size_t)KHOPS * NNODES * RWS,
                                 sdeg, isdeg, att + 1 * (KHOPS + 1));
    // Final: logits + fused log_softmax -> out (tensor cores)
    final_kernel<<<gridF, 128>>>(bufB, W2, b2, out, NNODES);
}

// round 14
// speedup vs baseline: 1.3732x; 1.0641x over previous
#include <cuda_runtime.h>
#include <cuda_fp16.h>
#include <cstdint>

#define NNODES 100000
#define NPAD   100096          // 782 * 128, padded row count for scratch
#define HDIM   128
#define RWS    10
#define KHOPS  4
#define CDIM   40
#define NSAMP  (KHOPS * RWS)   // 40
#define ANPB   8               // nodes per agg block (1 warp per node)

// Scratch buffers — __device__ globals (zero-init).
__device__ __half g_bufA[(size_t)NPAD * HDIM];
__device__ __half g_bufB[(size_t)NPAD * HDIM];
__device__ __half g_w0h[256 * 128];
__device__ __half g_w1h[128 * 128];
__device__ float  g_sdeg[NNODES];    // sqrt(deg)
__device__ float  g_isdeg[NNODES];   // rsqrt(deg)

// ---------------------------------------------------------------------------
// Tensor-core + async-copy primitives
// ---------------------------------------------------------------------------
__device__ __forceinline__ uint32_t smem_u32(const void* p) {
    return (uint32_t)__cvta_generic_to_shared(p);
}
__device__ __forceinline__ void ldsm_x4(uint32_t* r, uint32_t a) {
    asm volatile("ldmatrix.sync.aligned.m8n8.x4.shared.b16 {%0,%1,%2,%3}, [%4];"
                 : "=r"(r[0]), "=r"(r[1]), "=r"(r[2]), "=r"(r[3]) : "r"(a));
}
__device__ __forceinline__ void ldsm_x4_t(uint32_t* r, uint32_t a) {
    asm volatile("ldmatrix.sync.aligned.m8n8.x4.trans.shared.b16 {%0,%1,%2,%3}, [%4];"
                 : "=r"(r[0]), "=r"(r[1]), "=r"(r[2]), "=r"(r[3]) : "r"(a));
}
__device__ __forceinline__ void mma16816(float* c, const uint32_t* a, const uint32_t* b) {
    asm volatile(
        "mma.sync.aligned.m16n8k16.row.col.f32.f16.f16.f32 "
        "{%0,%1,%2,%3}, {%4,%5,%6,%7}, {%8,%9}, {%0,%1,%2,%3};"
        : "+f"(c[0]), "+f"(c[1]), "+f"(c[2]), "+f"(c[3])
        : "r"(a[0]), "r"(a[1]), "r"(a[2]), "r"(a[3]), "r"(b[0]), "r"(b[1]));
}
__device__ __forceinline__ void cp16(uint32_t dst, const void* src) {
    asm volatile("cp.async.cg.shared.global [%0], [%1], 16;"
                 :: "r"(dst), "l"(src));
}
__device__ __forceinline__ void cp16z(uint32_t dst, const void* src, int sz) {
    asm volatile("cp.async.cg.shared.global [%0], [%1], 16, %2;"
                 :: "r"(dst), "l"(src), "r"(sz));
}
__device__ __forceinline__ void cp_commit() {
    asm volatile("cp.async.commit_group;");
}
template <int N>
__device__ __forceinline__ void cp_wait() {
    asm volatile("cp.async.wait_group %0;" :: "n"(N));
}

// ---------------------------------------------------------------------------
// Prep: deg sqrt/rsqrt + convert W0/W1 to fp16 once.
// ---------------------------------------------------------------------------
__global__ void __launch_bounds__(256) prep_kernel(
    const float* __restrict__ deg,
    const float* __restrict__ W0, const float* __restrict__ W1)
{
    const int i = blockIdx.x * 256 + threadIdx.x;
    if (i < NNODES) {
        float d = deg[i];
        g_sdeg[i]  = sqrtf(d);
        g_isdeg[i] = rsqrtf(d);
    }
    if (i < 256 * 128) g_w0h[i] = __float2half_rn(W0[i]);
    if (i < 128 * 128) g_w1h[i] = __float2half_rn(W1[i]);
}

// ---------------------------------------------------------------------------
// GEMM layer 0: C[NPAD x 128] = A32[M x 256] @ Wh[256 x 128] + bias, fp16 out.
// BM=128, BN=128, BK=16, 256 threads, 8 warps (4x2), 32x64 per warp.
// fp32 A cp.async 4-stage ring + in-smem convert; fp16 B cp.async 4-stage
// ring. smem ~62KB -> 2 CTAs/SM (vs 1 with full-W staging).
// ---------------------------------------------------------------------------
template <int K>
__global__ void __launch_bounds__(256) hgemm_f32a(
    const float* __restrict__ A, const __half* __restrict__ Wh,
    const float* __restrict__ bias, __half* __restrict__ C, int M)
{
    constexpr int S  = 4;
    constexpr int AP = 24;    // As row pitch (halves)
    constexpr int BP = 136;   // Bs row pitch (halves)
    constexpr int KT = K / 16;

    __shared__ __half Bs[S][16 * BP];     // 17.4 KB
    __shared__ float  A32[S][128 * 16];   // 32 KB
    __shared__ __half As[2][128 * AP];    // 12.3 KB

    const int t    = threadIdx.x;
    const int lane = t & 31;
    const int wid  = t >> 5;
    const int warpRow = wid >> 1;
    const int warpCol = wid & 1;
    const int blockRow = blockIdx.x * 128;

    const int a_row = t >> 1;
    const int a_kg  = (t & 1) * 8;
    const int grow  = blockRow + a_row;
    const bool a_valid = (grow < M);

    const int b_r = t >> 4;            // 0..15
    const int b_n = (t & 15) * 8;      // 0..120

    auto issue = [&](int s, int k0) {
        const float* src = A + (size_t)grow * K + k0 + a_kg;
        uint32_t d = smem_u32(&A32[s][a_row * 16 + a_kg]);
        const int sz = a_valid ? 16 : 0;
        cp16z(d,      src,     sz);
        cp16z(d + 16, src + 4, sz);
        cp16(smem_u32(&Bs[s][b_r * BP + b_n]),
             Wh + (size_t)(k0 + b_r) * 128 + b_n);
        cp_commit();
    };

    issue(0, 0);
    issue(1, 16);
    issue(2, 32);

    float acc[2][8][4];
    #pragma unroll
    for (int mt = 0; mt < 2; mt++)
        #pragma unroll
        for (int nt = 0; nt < 8; nt++)
            #pragma unroll
            for (int q = 0; q < 4; q++) acc[mt][nt][q] = 0.0f;

    const int a_lr = lane & 15;
    const int a_lk = (lane >> 4) * 8;
    const int b_lr = (lane & 7) + ((lane >> 3) & 1) * 8;
    const int b_lcg = (lane >> 4) * 8;

    for (int kt = 0; kt < KT; kt++) {
        cp_wait<2>();
        __syncthreads();

        // Issue stage kt+S-1 (its buffers were consumed in iteration kt-1;
        // the barrier above orders those reads before these writes).
        if (kt + S - 1 < KT) issue((kt + S - 1) % S, (kt + S - 1) * 16);
        else                 cp_commit();

        // Convert this stage's fp32 A to fp16 ldmatrix layout.
        const int rb = kt & 1;
        {
            const float* s32 = &A32[kt % S][a_row * 16 + a_kg];
            float4 v0 = *(const float4*)s32;
            float4 v1 = *(const float4*)(s32 + 4);
            __half h8[8];
            h8[0] = __float2half_rn(v0.x); h8[1] = __float2half_rn(v0.y);
            h8[2] = __float2half_rn(v0.z); h8[3] = __float2half_rn(v0.w);
            h8[4] = __float2half_rn(v1.x); h8[5] = __float2half_rn(v1.y);
            h8[6] = __float2half_rn(v1.z); h8[7] = __float2half_rn(v1.w);
            *(uint4*)&As[rb][a_row * AP + a_kg] = *(uint4*)h8;
        }
        __syncthreads();

        uint32_t a[2][4];
        #pragma unroll
        for (int mt = 0; mt < 2; mt++) {
            ldsm_x4(a[mt], smem_u32(
                &As[rb][(warpRow * 32 + mt * 16 + a_lr) * AP + a_lk]));
        }

        uint32_t b[8][2];
        #pragma unroll
        for (int ntp = 0; ntp < 4; ntp++) {
            uint32_t r4[4];
            ldsm_x4_t(r4, smem_u32(
                &Bs[kt % S][b_lr * BP + warpCol * 64 + ntp * 16 + b_lcg]));
            b[ntp * 2 + 0][0] = r4[0]; b[ntp * 2 + 0][1] = r4[1];
            b[ntp * 2 + 1][0] = r4[2]; b[ntp * 2 + 1][1] = r4[3];
        }

        #pragma unroll
        for (int mt = 0; mt < 2; mt++)
            #pragma unroll
            for (int nt = 0; nt < 8; nt++)
                mma16816(acc[mt][nt], a[mt], b[nt]);
    }

    // Epilogue: bias (fp32) -> fp16 half2 stores. Padded scratch: no guards.
    float2 bb[8];
    #pragma unroll
    for (int nt = 0; nt < 8; nt++) {
        const int col = warpCol * 64 + nt * 8 + (lane & 3) * 2;
        bb[nt] = *(const float2*)&bias[col];
    }
    #pragma unroll
    for (int mt = 0; mt < 2; mt++) {
        const int r0 = blockRow + warpRow * 32 + mt * 16 + (lane >> 2);
        const int r1 = r0 + 8;
        #pragma unroll
        for (int nt = 0; nt < 8; nt++) {
            const int col = warpCol * 64 + nt * 8 + (lane & 3) * 2;
            *(__half2*)(C + (size_t)r0 * 128 + col) =
                __floats2half2_rn(acc[mt][nt][0] + bb[nt].x,
                                  acc[mt][nt][1] + bb[nt].y);
            *(__half2*)(C + (size_t)r1 * 128 + col) =
                __floats2half2_rn(acc[mt][nt][2] + bb[nt].x,
                                  acc[mt][nt][3] + bb[nt].y);
        }
    }
}

// ---------------------------------------------------------------------------
// GEMM layer 1: fp16 A (padded buffer), fp16 W ring. Same tile shape.
// ---------------------------------------------------------------------------
template <int K>
__global__ void __launch_bounds__(256) hgemm_f16a(
    const __half* __restrict__ A, const __half* __restrict__ Wh,
    const float* __restrict__ bias, __half* __restrict__ C)
{
    constexpr int S  = 4;
    constexpr int AP = 24;
    constexpr int BP = 136;
    constexpr int KT = K / 16;

    __shared__ __half As[S][128 * AP];
    __shared__ __half Bs[S][16 * BP];

    const int t    = threadIdx.x;
    const int lane = t & 31;
    const int wid  = t >> 5;
    const int warpRow = wid >> 1;
    const int warpCol = wid & 1;
    const int blockRow = blockIdx.x * 128;

    const int a_row = t >> 1;
    const int a_kg  = (t & 1) * 8;
    const int grow  = blockRow + a_row;

    const int b_r = t >> 4;
    const int b_n = (t & 15) * 8;

    auto issue = [&](int s, int k0) {
        cp16(smem_u32(&As[s][a_row * AP + a_kg]),
             A + (size_t)grow * K + k0 + a_kg);
        cp16(smem_u32(&Bs[s][b_r * BP + b_n]),
             Wh + (size_t)(k0 + b_r) * 128 + b_n);
        cp_commit();
    };

    issue(0, 0);
    issue(1, 16);
    issue(2, 32);

    float acc[2][8][4];
    #pragma unroll
    for (int mt = 0; mt < 2; mt++)
        #pragma unroll
        for (int nt = 0; nt < 8; nt++)
            #pragma unroll
            for (int q = 0; q < 4; q++) acc[mt][nt][q] = 0.0f;

    const int a_lr = lane & 15;
    const int a_lk = (lane >> 4) * 8;
    const int b_lr = (lane & 7) + ((lane >> 3) & 1) * 8;
    const int b_lcg = (lane >> 4) * 8;

    for (int kt = 0; kt < KT; kt++) {
        cp_wait<2>();
        __syncthreads();

        if (kt + S - 1 < KT) issue((kt + S - 1) % S, (kt + S - 1) * 16);
        else                 cp_commit();

        const int rb = kt % S;
        uint32_t a[2][4];
        #pragma unroll
        for (int mt = 0; mt < 2; mt++) {
            ldsm_x4(a[mt], smem_u32(
                &As[rb][(warpRow * 32 + mt * 16 + a_lr) * AP + a_lk]));
        }

        uint32_t b[8][2];
        #pragma unroll
        for (int ntp = 0; ntp < 4; ntp++) {
            uint32_t r4[4];
            ldsm_x4_t(r4, smem_u32(
                &Bs[rb][b_lr * BP + warpCol * 64 + ntp * 16 + b_lcg]));
            b[ntp * 2 + 0][0] = r4[0]; b[ntp * 2 + 0][1] = r4[1];
            b[ntp * 2 + 1][0] = r4[2]; b[ntp * 2 + 1][1] = r4[3];
        }

        #pragma unroll
        for (int mt = 0; mt < 2; mt++)
            #pragma unroll
            for (int nt = 0; nt < 8; nt++)
                mma16816(acc[mt][nt], a[mt], b[nt]);
    }

    float2 bb[8];
    #pragma unroll
    for (int nt = 0; nt < 8; nt++) {
        const int col = warpCol * 64 + nt * 8 + (lane & 3) * 2;
        bb[nt] = *(const float2*)&bias[col];
    }
    #pragma unroll
    for (int mt = 0; mt < 2; mt++) {
        const int r0 = blockRow + warpRow * 32 + mt * 16 + (lane >> 2);
        const int r1 = r0 + 8;
        #pragma unroll
        for (int nt = 0; nt < 8; nt++) {
            const int col = warpCol * 64 + nt * 8 + (lane & 3) * 2;
            *(__half2*)(C + (size_t)r0 * 128 + col) =
                __floats2half2_rn(acc[mt][nt][0] + bb[nt].x,
                                  acc[mt][nt][1] + bb[nt].y);
            *(__half2*)(C + (size_t)r1 * 128 + col) =
                __floats2half2_rn(acc[mt][nt][2] + bb[nt].x,
                                  acc[mt][nt][3] + bb[nt].y);
        }
    }
}

// ---------------------------------------------------------------------------
// Random-walk aggregation + ReLU. One WARP per node, fp16 (no cvt — the
// R11 fp8 failure was cvt ALU, not the layout). Per sample per warp:
// LDS.64 + IMAD + LDG.64 + 2 HFMA2 = 5 instr (vs ~14 in 16-lane layout),
// same wavefront count. 8-deep gather batching. Dual accumulator sets.
// ---------------------------------------------------------------------------
__global__ void __launch_bounds__(256) agg_kernel(
    const __half* __restrict__ hin, __half* __restrict__ hout,
    const int* __restrict__ ends_l,
    const float* __restrict__ sdeg,
    const float* __restrict__ isdeg,
    const float* __restrict__ att_l)
{
    __shared__ int2 sp[ANPB][NSAMP];     // {endpoint idx, half2(w,w) bits}

    const int n0 = blockIdx.x * ANPB;
    const int t  = threadIdx.x;

    #pragma unroll
    for (int i = t; i < ANPB * NSAMP; i += 256) {
        const int nl = i / NSAMP;
        const int s  = i - nl * NSAMP;
        const int k  = s / RWS;
        const int r  = s - k * RWS;
        const int n  = n0 + nl;
        const int e  = ends_l[k * (NNODES * RWS) + n * RWS + r];
        const float w = att_l[k + 1] * (1.0f / RWS) * sdeg[n] * isdeg[e];
        __half2 wh = __float2half2_rn(w);
        int2 p; p.x = e; p.y = *(int*)&wh;
        sp[nl][s] = p;
    }
    __syncthreads();

    const int wid  = t >> 5;             // node within block
    const int lane = t & 31;             // 4 halves (8B) per lane
    const int n    = n0 + wid;
    const __half* lbase = hin + lane * 4;

    __half2 a0, a1, b0, b1;
    {
        const __half2 att0h = __float2half2_rn(att_l[0]);
        uint2 sv = *(const uint2*)(lbase + ((size_t)n << 7));
        a0 = __hmul2(att0h, *(const __half2*)&sv.x);
        a1 = __hmul2(att0h, *(const __half2*)&sv.y);
        b0 = __floats2half2_rn(0.f, 0.f);
        b1 = b0;
    }

    #pragma unroll
    for (int s = 0; s < NSAMP; s += 8) {
        int2  pp[8];
        uint2 vv[8];
        #pragma unroll
        for (int j = 0; j < 8; j++) pp[j] = sp[wid][s + j];
        #pragma unroll
        for (int j = 0; j < 8; j++)
            vv[j] = *(const uint2*)(lbase + ((size_t)pp[j].x << 7));
        #pragma unroll
        for (int j = 0; j < 8; j += 2) {
            const __half2 w0 = *(const __half2*)&pp[j].y;
            const __half2 w1 = *(const __half2*)&pp[j + 1].y;
            a0 = __hfma2(w0, *(const __half2*)&vv[j].x,     a0);
            a1 = __hfma2(w0, *(const __half2*)&vv[j].y,     a1);
            b0 = __hfma2(w1, *(const __half2*)&vv[j + 1].x, b0);
            b1 = __hfma2(w1, *(const __half2*)&vv[j + 1].y, b1);
        }
    }

    // Combine fp32, ReLU, store 4 fp16 (256B per warp, coalesced).
    float2 u0 = __half22float2(a0), u1 = __half22float2(b0);
    float2 v0 = __half22float2(a1), v1 = __half22float2(b1);
    uint2 o;
    ((__half2*)&o.x)[0] = __floats2half2_rn(fmaxf(u0.x + u1.x, 0.f),
                                            fmaxf(u0.y + u1.y, 0.f));
    ((__half2*)&o.y)[0] = __floats2half2_rn(fmaxf(v0.x + v1.x, 0.f),
                                            fmaxf(v0.y + v1.y, 0.f));
    *(uint2*)(hout + (size_t)n * HDIM + lane * 4) = o;
}

// ---------------------------------------------------------------------------
// Final: logits = h @ W2 + b2 (HMMA, N padded 40->64), fused log_softmax.
// BM=64, 4 warps, warp tile 16x64. Padded cols: bias -1e30 -> never max.
// ---------------------------------------------------------------------------
__global__ void __launch_bounds__(128) final_kernel(
    const __half* __restrict__ h, const float* __restrict__ W2,
    const float* __restrict__ b2, float* __restrict__ out, int M)
{
    constexpr int AP = 136;  // As pitch (rows of 128 halves)
    constexpr int BP = 72;   // Bs pitch (rows of 64 halves)
    __shared__ __half As[64 * AP];
    __shared__ __half Bs[128 * BP];

    const int t    = threadIdx.x;
    const int lane = t & 31;
    const int wid  = t >> 5;
    const int blockRow = blockIdx.x * 64;

    // Stage B: W2 [128 k x 40] -> padded fp16 [128 x 64].
    {
        const int r = t;
        __half h8[8];
        #pragma unroll
        for (int c0 = 0; c0 < 64; c0 += 8) {
            #pragma unroll
            for (int q = 0; q < 8; q++) {
                const int c = c0 + q;
                h8[q] = (c < CDIM) ? __float2half_rn(W2[r * CDIM + c])
                                   : __float2half_rn(0.0f);
            }
            *(uint4*)&Bs[r * BP + c0] = *(uint4*)h8;
        }
    }
    // Stage A: h rows [blockRow..+63] x 128 halves (padded buffer, no guard).
    {
        const int a_row = t >> 1;
        const int kg    = (t & 1) * 64;
        const uint4* src = (const uint4*)(h + (size_t)(blockRow + a_row) * HDIM + kg);
        #pragma unroll
        for (int q = 0; q < 8; q++)
            *(uint4*)&As[a_row * AP + kg + q * 8] = src[q];
    }
    __syncthreads();

    const int a_lr = lane & 15;
    const int a_lk = (lane >> 4) * 8;
    const int b_lr = (lane & 7) + ((lane >> 3) & 1) * 8;
    const int b_lcg = (lane >> 4) * 8;

    float acc[8][4];
    #pragma unroll
    for (int nt = 0; nt < 8; nt++)
        #pragma unroll
        for (int q = 0; q < 4; q++) acc[nt][q] = 0.0f;

    #pragma unroll
    for (int k0 = 0; k0 < HDIM; k0 += 16) {
        uint32_t a[4];
        ldsm_x4(a, smem_u32(&As[(wid * 16 + a_lr) * AP + k0 + a_lk]));

        uint32_t b[8][2];
        #pragma unroll
        for (int ntp = 0; ntp < 4; ntp++) {
            uint32_t r4[4];
            ldsm_x4_t(r4, smem_u32(&Bs[(k0 + b_lr) * BP + ntp * 16 + b_lcg]));
            b[ntp * 2 + 0][0] = r4[0]; b[ntp * 2 + 0][1] = r4[1];
            b[ntp * 2 + 1][0] = r4[2]; b[ntp * 2 + 1][1] = r4[3];
        }

        #pragma unroll
        for (int nt = 0; nt < 8; nt++)
            mma16816(acc[nt], a, b[nt]);
    }

    float v0[8][2], v1[8][2];
    #pragma unroll
    for (int nt = 0; nt < 8; nt++) {
        const int col = nt * 8 + (lane & 3) * 2;
        const float bx = (col     < CDIM) ? b2[col]     : -1e30f;
        const float by = (col + 1 < CDIM) ? b2[col + 1] : -1e30f;
        v0[nt][0] = acc[nt][0] + bx; v0[nt][1] = acc[nt][1] + by;
        v1[nt][0] = acc[nt][2] + bx; v1[nt][1] = acc[nt][3] + by;
    }

    float m0 = -1e30f, m1 = -1e30f;
    #pragma unroll
    for (int nt = 0; nt < 8; nt++) {
        m0 = fmaxf(m0, fmaxf(v0[nt][0], v0[nt][1]));
        m1 = fmaxf(m1, fmaxf(v1[nt][0], v1[nt][1]));
    }
    m0 = fmaxf(m0, __shfl_xor_sync(0xffffffffu, m0, 1));
    m0 = fmaxf(m0, __shfl_xor_sync(0xffffffffu, m0, 2));
    m1 = fmaxf(m1, __shfl_xor_sync(0xffffffffu, m1, 1));
    m1 = fmaxf(m1, __shfl_xor_sync(0xffffffffu, m1, 2));

    float s0 = 0.0f, s1 = 0.0f;
    #pragma unroll
    for (int nt = 0; nt < 8; nt++) {
        s0 += __expf(v0[nt][0] - m0) + __expf(v0[nt][1] - m0);
        s1 += __expf(v1[nt][0] - m1) + __expf(v1[nt][1] - m1);
    }
    s0 += __shfl_xor_sync(0xffffffffu, s0, 1);
    s0 += __shfl_xor_sync(0xffffffffu, s0, 2);
    s1 += __shfl_xor_sync(0xffffffffu, s1, 1);
    s1 += __shfl_xor_sync(0xffffffffu, s1, 2);

    const float lse0 = m0 + __logf(s0);
    const float lse1 = m1 + __logf(s1);

    const int r0 = blockRow + wid * 16 + (lane >> 2);
    const int r1 = r0 + 8;
    #pragma unroll
    for (int nt = 0; nt < 5; nt++) {        // cols 0..39 only
        const int col = nt * 8 + (lane & 3) * 2;
        if (r0 < M) {
            float2 w = make_float2(v0[nt][0] - lse0, v0[nt][1] - lse0);
            *(float2*)(out + (size_t)r0 * CDIM + col) = w;
        }
        if (r1 < M) {
            float2 w = make_float2(v1[nt][0] - lse1, v1[nt][1] - lse1);
            *(float2*)(out + (size_t)r1 * CDIM + col) = w;
        }
    }
}

// ---------------------------------------------------------------------------
// Launch sequence. Inputs: x, degree, ends, att, W0, b0, W1, b1, W2, b2
// ---------------------------------------------------------------------------
extern "C" void kernel_launch(void* const* d_in, const int* in_sizes, int n_in,
                              void* d_out, int out_size)
{
    const float* x   = (const float*)d_in[0];
    const float* deg = (const float*)d_in[1];
    const int*   ends= (const int*)  d_in[2];
    const float* att = (const float*)d_in[3];
    const float* W0  = (const float*)d_in[4];
    const float* b0  = (const float*)d_in[5];
    const float* W1  = (const float*)d_in[6];
    const float* b1  = (const float*)d_in[7];
    const float* W2  = (const float*)d_in[8];
    const float* b2  = (const float*)d_in[9];
    float* out = (float*)d_out;

    __half *bufA, *bufB, *w0h, *w1h;
    float *sdeg, *isdeg;
    cudaGetSymbolAddress((void**)&bufA, g_bufA);
    cudaGetSymbolAddress((void**)&bufB, g_bufB);
    cudaGetSymbolAddress((void**)&w0h,  g_w0h);
    cudaGetSymbolAddress((void**)&w1h,  g_w1h);
    cudaGetSymbolAddress((void**)&sdeg, g_sdeg);
    cudaGetSymbolAddress((void**)&isdeg,g_isdeg);

    const int gridM   = NPAD / 128;               // 782
    const int gridF   = (NNODES + 63) / 64;       // 1563
    const int gridAgg = NNODES / ANPB;            // 12500

    prep_kernel<<<(NNODES + 255) / 256, 256>>>(deg, W0, W1);
    // Layer 0: h = x @ W0h + b0 -> bufA (fp16)
    hgemm_f32a<256><<<gridM, 256>>>(x, w0h, b0, bufA, NNODES);
    // Agg layer 0: bufA -> bufB (relu'd)
    agg_kernel<<<gridAgg, 256>>>(bufA, bufB,
                                 ends + 0 * (size_t)KHOPS * NNODES * RWS,
                                 sdeg, isdeg, att + 0 * (KHOPS + 1));
    // Layer 1: h = bufB @ W1h + b1 -> bufA
    hgemm_f16a<128><<<gridM, 256>>>(bufB, w1h, b1, bufA);
    // Agg layer 1: bufA -> bufB (relu'd)
    agg_kernel<<<gridAgg, 256>>>(bufA, bufB,
                                 ends + 1 * (size_t)KHOPS * NNODES * RWS,
                                 sdeg, isdeg, att + 1 * (KHOPS + 1));
    // Final: logits + fused log_softmax -> out (tensor cores)
    final_kernel<<<gridF, 128>>>(bufB, W2, b2, out, NNODES);
}